// round 7
// baseline (speedup 1.0000x reference)
#include <cuda_runtime.h>
#include <cstdint>

#define NT 512

using u64 = unsigned long long;

// ---- packed f32x2 helpers (sm_103a) ----
__device__ __forceinline__ u64 pk2(float lo, float hi) {
    u64 r; asm("mov.b64 %0, {%1, %2};" : "=l"(r) : "f"(lo), "f"(hi)); return r;
}
__device__ __forceinline__ float2 up2(u64 v) {
    float2 r; asm("mov.b64 {%0, %1}, %2;" : "=f"(r.x), "=f"(r.y) : "l"(v)); return r;
}
__device__ __forceinline__ u64 fma2(u64 a, u64 b, u64 c) {
    u64 d; asm("fma.rn.f32x2 %0, %1, %2, %3;" : "=l"(d) : "l"(a), "l"(b), "l"(c)); return d;
}
__device__ __forceinline__ u64 add2(u64 a, u64 b) {
    u64 d; asm("add.rn.f32x2 %0, %1, %2;" : "=l"(d) : "l"(a), "l"(b)); return d;
}

// Process one z-adjacent pair of cells (z0 even, cells z0 and z0+1) of one level.
// State layout per level: s[buf][c][x][y][z] planar, channel stride S = N^3.
__device__ __forceinline__ void cell_pair(
    int ln,            // log2(N)
    int hasBelow, int hasAbove,
    const float* __restrict__ oS,   // old self base (buf applied)
    const float* __restrict__ oB,   // old finer-level base (below source)
    const float* __restrict__ oA,   // old coarser-level base (above source)
    float* __restrict__ nS,         // new self base
    const u64* __restrict__ w1, const u64* __restrict__ b1,
    const u64* __restrict__ w2, const u64* __restrict__ b2,
    int pi)
{
    const int N = 1 << ln;
    const int S = 1 << (3 * ln);
    const int z0  = (pi & ((1 << (ln - 1)) - 1)) << 1;
    const int rem = pi >> (ln - 1);
    const int y = rem & (N - 1);
    const int x = rem >> ln;
    const int cidx = ((x << ln) + y) * N + z0;

    u64 h2[16];
    const u64 NEG6 = 0xC0C00000C0C00000ULL;   // (-6.f, -6.f)

    // perception: identity + 6-neighbor laplacian, per channel, zero padding
    #pragma unroll
    for (int c = 0; c < 4; c++) {
        const float* pc = oS + c * S;
        u64 ctr = *reinterpret_cast<const u64*>(pc + cidx);
        float2 cf = up2(ctr);
        u64 acc = 0ULL;
        if (x > 0)     acc = add2(acc, *reinterpret_cast<const u64*>(pc + cidx - N * N));
        if (x < N - 1) acc = add2(acc, *reinterpret_cast<const u64*>(pc + cidx + N * N));
        if (y > 0)     acc = add2(acc, *reinterpret_cast<const u64*>(pc + cidx - N));
        if (y < N - 1) acc = add2(acc, *reinterpret_cast<const u64*>(pc + cidx + N));
        float zm = (z0 > 0)     ? pc[cidx - 1] : 0.f;
        float zp = (z0 + 2 < N) ? pc[cidx + 2] : 0.f;
        acc = add2(acc, pk2(zm, cf.x));
        acc = add2(acc, pk2(cf.y, zp));
        h2[2 * c]     = ctr;
        h2[2 * c + 1] = fma2(ctr, NEG6, acc);
    }

    // below message: avgpool2 of finer level (8 fine cells per coarse cell)
    if (hasBelow) {
        const int Nf = N << 1, Sf = S << 3;
        const int fz = z0 << 1;   // fine z run: fz..fz+3 covers both pair cells
        #pragma unroll
        for (int c = 0; c < 4; c++) {
            const float* pf = oB + c * Sf;
            float lo = 0.f, hi = 0.f;
            #pragma unroll
            for (int dx = 0; dx < 2; dx++)
                #pragma unroll
                for (int dy = 0; dy < 2; dy++) {
                    const float4 v = *reinterpret_cast<const float4*>(
                        pf + (((2 * x + dx) * Nf) + (2 * y + dy)) * Nf + fz);
                    lo += v.x + v.y; hi += v.z + v.w;
                }
            h2[8 + c] = pk2(lo * 0.125f, hi * 0.125f);
        }
    } else {
        h2[8] = h2[9] = h2[10] = h2[11] = 0ULL;
    }

    // above message: upsample2 of coarser level (same coarse cell for both pair cells)
    if (hasAbove) {
        const int Nc = N >> 1, Sc = S >> 3;
        const int ci = (((x >> 1) * Nc) + (y >> 1)) * Nc + (z0 >> 1);
        #pragma unroll
        for (int c = 0; c < 4; c++) {
            float v = oA[c * Sc + ci];
            h2[12 + c] = pk2(v, v);
        }
    } else {
        h2[12] = h2[13] = h2[14] = h2[15] = 0ULL;
    }

    // MLP 16 -> 32 (relu) -> 4, both cells packed in f32x2 lanes.
    // Weight/bias tables read via 16B LDS.128 (ulonglong2) — all 16B aligned.
    u64 o2[4];
    {
        const ulonglong2* b2v = reinterpret_cast<const ulonglong2*>(b2);
        ulonglong2 ba = b2v[0], bb = b2v[1];
        o2[0] = ba.x; o2[1] = ba.y; o2[2] = bb.x; o2[3] = bb.y;
    }

    #pragma unroll
    for (int hf = 0; hf < 2; hf++) {
        u64 acc[16];
        {
            const ulonglong2* b1v = reinterpret_cast<const ulonglong2*>(b1 + hf * 16);
            #pragma unroll
            for (int h = 0; h < 8; h++) {
                ulonglong2 bb = b1v[h];
                acc[2 * h]     = bb.x;
                acc[2 * h + 1] = bb.y;
            }
        }
        #pragma unroll
        for (int c = 0; c < 16; c++) {
            const u64 hv = h2[c];
            const ulonglong2* wrow =
                reinterpret_cast<const ulonglong2*>(w1 + c * 32 + hf * 16);
            #pragma unroll
            for (int h = 0; h < 8; h++) {
                ulonglong2 w = wrow[h];
                acc[2 * h]     = fma2(hv, w.x, acc[2 * h]);
                acc[2 * h + 1] = fma2(hv, w.y, acc[2 * h + 1]);
            }
        }
        #pragma unroll
        for (int h = 0; h < 16; h++) {
            float2 a = up2(acc[h]);
            u64 r = pk2(fmaxf(a.x, 0.f), fmaxf(a.y, 0.f));
            const ulonglong2* w2v =
                reinterpret_cast<const ulonglong2*>(w2 + (hf * 16 + h) * 4);
            ulonglong2 wa = w2v[0], wb = w2v[1];
            o2[0] = fma2(r, wa.x, o2[0]);
            o2[1] = fma2(r, wa.y, o2[1]);
            o2[2] = fma2(r, wb.x, o2[2]);
            o2[3] = fma2(r, wb.y, o2[3]);
        }
    }

    // residual update + clip, write new state
    const u64 P1 = 0x3DCCCCCD3DCCCCCDULL;   // (0.1f, 0.1f)
    #pragma unroll
    for (int cc = 0; cc < 4; cc++) {
        u64 nv = fma2(o2[cc], P1, h2[2 * cc]);
        float2 n = up2(nv);
        float n0 = fminf(fmaxf(n.x, -1.f), 1.f);
        float n1 = fminf(fmaxf(n.y, -1.f), 1.f);
        *reinterpret_cast<u64*>(nS + cc * S + cidx) = pk2(n0, n1);
    }
}

// SMEM layout (floats):
//  S0: 2*4*4096 = 32768   @ 0
//  S1: 2*4*512  = 4096    @ 32768
//  S2: 2*4*64   = 512     @ 36864
//  W1D (u64 dup): 3*16*32 = 1536 u64 = 3072 f @ 37376  (byte 149504, 16B aligned)
//  B1D: 3*32 = 96 u64 = 192 f  @ 40448                 (byte 161792, 16B aligned)
//  W2D: 3*32*4 = 384 u64 = 768 f @ 40640               (byte 162560, 16B aligned)
//  B2D: 3*4 = 12 u64 = 24 f @ 41408                    (byte 165632, 16B aligned)
//  total 41432 floats = 165728 bytes
__global__ void __launch_bounds__(NT, 1) nca_kernel(
    const float* __restrict__ x,
    const float* __restrict__ w1g, const float* __restrict__ b1g,
    const float* __restrict__ w2g, const float* __restrict__ b2g,
    const float* __restrict__ clsw, const float* __restrict__ clsb,
    float* __restrict__ out)
{
    extern __shared__ float sm[];
    float* S0 = sm;
    float* S1 = sm + 32768;
    float* S2 = sm + 36864;
    u64* W1D = reinterpret_cast<u64*>(sm + 37376);
    u64* B1D = reinterpret_cast<u64*>(sm + 40448);
    u64* W2D = reinterpret_cast<u64*>(sm + 40640);
    u64* B2D = reinterpret_cast<u64*>(sm + 41408);

    const int tid = threadIdx.x;
    const int b = blockIdx.x;

    // load + duplicate-pack weights
    for (int i = tid; i < 1536; i += NT) { float w = w1g[i]; W1D[i] = pk2(w, w); }
    for (int i = tid; i < 96;   i += NT) { float w = b1g[i]; B1D[i] = pk2(w, w); }
    for (int i = tid; i < 384;  i += NT) { float w = w2g[i]; W2D[i] = pk2(w, w); }
    if (tid < 12) { float w = b2g[tid]; B2D[tid] = pk2(w, w); }

    // zero buf0 of all levels (buf1 is fully written by step 0)
    for (int i = tid; i < 16384; i += NT) S0[i] = 0.f;
    for (int i = tid; i < 2048;  i += NT) S1[i] = 0.f;
    for (int i = tid; i < 256;   i += NT) S2[i] = 0.f;
    __syncthreads();

    // input: thresholded pattern into channel 0, z = 8 slice of level 0, buf0
    {
        const float* xb = x + (size_t)b * 256;
        for (int i = tid; i < 256; i += NT) {
            S0[i * 16 + 8] = (xb[i] > 0.5f) ? 1.f : 0.f;
        }
    }
    __syncthreads();

    // 15 synchronous steps; pairs: L0 2048, L1 256, L2 32 -> 2336 items
    for (int step = 0; step < 15; step++) {
        const int ob = step & 1;
        const int nb = ob ^ 1;
        const float* o0 = S0 + ob * 16384;  float* n0p = S0 + nb * 16384;
        const float* o1 = S1 + ob * 2048;   float* n1p = S1 + nb * 2048;
        const float* o2 = S2 + ob * 256;    float* n2p = S2 + nb * 256;

        for (int it = tid; it < 2336; it += NT) {
            int ln, hb, ha, pi;
            const float *oS, *oB, *oA;
            float* nS;
            const u64 *w1, *b1p, *w2, *b2p;
            if (it < 2048) {
                ln = 4; hb = 0; ha = 1; pi = it;
                oS = o0; oB = nullptr; oA = o1; nS = n0p;
                w1 = W1D;        b1p = B1D;      w2 = W2D;       b2p = B2D;
            } else if (it < 2304) {
                ln = 3; hb = 1; ha = 1; pi = it - 2048;
                oS = o1; oB = o0; oA = o2; nS = n1p;
                w1 = W1D + 512;  b1p = B1D + 32; w2 = W2D + 128; b2p = B2D + 4;
            } else {
                ln = 2; hb = 1; ha = 0; pi = it - 2304;
                oS = o2; oB = o1; oA = nullptr; nS = n2p;
                w1 = W1D + 1024; b1p = B1D + 64; w2 = W2D + 256; b2p = B2D + 8;
            }
            cell_pair(ln, hb, ha, oS, oB, oA, nS, w1, b1p, w2, b2p, pi);
        }
        __syncthreads();
    }

    // classification: feats = top level (buf1, after 15 steps), order (x,y,z,c)
    const float* top = S2 + 256;   // buf 1
    if (tid < 10) {
        float acc = clsb[tid];
        #pragma unroll 4
        for (int f = 0; f < 256; f++)
            acc += top[(f & 3) * 64 + (f >> 2)] * clsw[f * 10 + tid];
        out[(size_t)b * 10 + tid] = acc;
    }
}

extern "C" void kernel_launch(void* const* d_in, const int* in_sizes, int n_in,
                              void* d_out, int out_size) {
    const float* x   = (const float*)d_in[0];
    const float* w1  = (const float*)d_in[1];
    const float* b1  = (const float*)d_in[2];
    const float* w2  = (const float*)d_in[3];
    const float* b2  = (const float*)d_in[4];
    const float* cw  = (const float*)d_in[5];
    const float* cb  = (const float*)d_in[6];
    float* out = (float*)d_out;

    const int B = in_sizes[0] / 256;              // 2048
    const size_t smem = 41432 * sizeof(float);    // 165728 bytes

    cudaFuncSetAttribute(nca_kernel, cudaFuncAttributeMaxDynamicSharedMemorySize, (int)smem);
    nca_kernel<<<B, NT, smem>>>(x, w1, b1, w2, b2, cw, cb, out);
}

// round 13
// speedup vs baseline: 1.2016x; 1.2016x over previous
#include <cuda_runtime.h>
#include <cstdint>

#define NT 256

using u64 = unsigned long long;

// ---- packed f32x2 helpers (sm_103a) ----
__device__ __forceinline__ u64 pk2(float lo, float hi) {
    u64 r; asm("mov.b64 %0, {%1, %2};" : "=l"(r) : "f"(lo), "f"(hi)); return r;
}
__device__ __forceinline__ float2 up2(u64 v) {
    float2 r; asm("mov.b64 {%0, %1}, %2;" : "=f"(r.x), "=f"(r.y) : "l"(v)); return r;
}
__device__ __forceinline__ u64 fma2(u64 a, u64 b, u64 c) {
    u64 d; asm("fma.rn.f32x2 %0, %1, %2, %3;" : "=l"(d) : "l"(a), "l"(b), "l"(c)); return d;
}
__device__ __forceinline__ u64 add2(u64 a, u64 b) {
    u64 d; asm("add.rn.f32x2 %0, %1, %2;" : "=l"(d) : "l"(a), "l"(b)); return d;
}

// Process one z-QUAD (4 z-adjacent cells, z0 % 4 == 0) of one level.
// Pair a = cells (z0, z0+1), pair b = (z0+2, z0+3); one shared weight pass.
// State layout per level: s[buf][c][x][y][z] planar, channel stride S = N^3.
__device__ __forceinline__ void quad_cell(
    int ln, int hasBelow, int hasAbove,
    const float* __restrict__ oS, const float* __restrict__ oB,
    const float* __restrict__ oA, float* __restrict__ nS,
    const u64* __restrict__ w1, const u64* __restrict__ b1,
    const u64* __restrict__ w2, const u64* __restrict__ b2,
    int u)   // quad index within level: u = ((x<<ln)+y)*(N/4) + zq
{
    const int N = 1 << ln;
    const int S = 1 << (3 * ln);
    const int zq  = u & ((N >> 2) - 1);
    const int rem = u >> (ln - 2);
    const int y = rem & (N - 1);
    const int x = rem >> ln;
    const int z0 = zq << 2;
    const int cidx = ((x << ln) + y) * N + z0;   // 4-float aligned

    u64 h2a[16], h2b[16];
    const u64 NEG6 = 0xC0C00000C0C00000ULL;   // (-6.f, -6.f)

    // perception: identity + 6-neighbor laplacian over the quad
    #pragma unroll
    for (int c = 0; c < 4; c++) {
        const float* pc = oS + c * S;
        ulonglong2 ctr = *reinterpret_cast<const ulonglong2*>(pc + cidx); // (v0,v1),(v2,v3)
        u64 aL = 0ULL, aH = 0ULL;
        if (x > 0)     { ulonglong2 t = *reinterpret_cast<const ulonglong2*>(pc + cidx - N * N); aL = add2(aL, t.x); aH = add2(aH, t.y); }
        if (x < N - 1) { ulonglong2 t = *reinterpret_cast<const ulonglong2*>(pc + cidx + N * N); aL = add2(aL, t.x); aH = add2(aH, t.y); }
        if (y > 0)     { ulonglong2 t = *reinterpret_cast<const ulonglong2*>(pc + cidx - N);     aL = add2(aL, t.x); aH = add2(aH, t.y); }
        if (y < N - 1) { ulonglong2 t = *reinterpret_cast<const ulonglong2*>(pc + cidx + N);     aL = add2(aL, t.x); aH = add2(aH, t.y); }
        float zm = (z0 > 0)     ? pc[cidx - 1] : 0.f;
        float zp = (z0 + 4 < N) ? pc[cidx + 4] : 0.f;
        float2 c01 = up2(ctr.x), c23 = up2(ctr.y);
        u64 mid = pk2(c01.y, c23.x);          // (v1, v2)
        aL = add2(aL, pk2(zm, c01.x));        // cell0 += zm, cell1 += v0
        aL = add2(aL, mid);                   // cell0 += v1, cell1 += v2
        aH = add2(aH, mid);                   // cell2 += v1, cell3 += v2
        aH = add2(aH, pk2(c23.y, zp));        // cell2 += v3, cell3 += zp
        h2a[2 * c]     = ctr.x;
        h2a[2 * c + 1] = fma2(ctr.x, NEG6, aL);
        h2b[2 * c]     = ctr.y;
        h2b[2 * c + 1] = fma2(ctr.y, NEG6, aH);
    }

    // below message: avgpool2 of finer level; fine z run fz..fz+7 covers the quad
    if (hasBelow) {
        const int Nf = N << 1, Sf = S << 3;
        const int fz = z0 << 1;
        #pragma unroll
        for (int c = 0; c < 4; c++) {
            const float* pf = oB + c * Sf;
            float la = 0.f, ha = 0.f, lb = 0.f, hb = 0.f;
            #pragma unroll
            for (int dx = 0; dx < 2; dx++)
                #pragma unroll
                for (int dy = 0; dy < 2; dy++) {
                    const float* base = pf + ((2 * x + dx) * Nf + (2 * y + dy)) * Nf + fz;
                    const float4 v0 = *reinterpret_cast<const float4*>(base);
                    const float4 v1 = *reinterpret_cast<const float4*>(base + 4);
                    la += v0.x + v0.y;  ha += v0.z + v0.w;
                    lb += v1.x + v1.y;  hb += v1.z + v1.w;
                }
            h2a[8 + c] = pk2(la * 0.125f, ha * 0.125f);
            h2b[8 + c] = pk2(lb * 0.125f, hb * 0.125f);
        }
    } else {
        h2a[8] = h2a[9] = h2a[10] = h2a[11] = 0ULL;
        h2b[8] = h2b[9] = h2b[10] = h2b[11] = 0ULL;
    }

    // above message: upsample2 of coarser level; quad maps to 2 consecutive coarse z
    if (hasAbove) {
        const int Nc = N >> 1, Sc = S >> 3;
        const int ci = ((x >> 1) * Nc + (y >> 1)) * Nc + (z0 >> 1);   // even -> 8B aligned
        #pragma unroll
        for (int c = 0; c < 4; c++) {
            float2 v = up2(*reinterpret_cast<const u64*>(oA + c * Sc + ci));
            h2a[12 + c] = pk2(v.x, v.x);
            h2b[12 + c] = pk2(v.y, v.y);
        }
    } else {
        h2a[12] = h2a[13] = h2a[14] = h2a[15] = 0ULL;
        h2b[12] = h2b[13] = h2b[14] = h2b[15] = 0ULL;
    }

    // MLP 16 -> 32 (relu) -> 4 for both pairs, one weight pass.
    // Hidden computed in 4 quarters of 8 units to bound registers.
    u64 o2a[4], o2b[4];
    {
        const ulonglong2* b2v = reinterpret_cast<const ulonglong2*>(b2);
        ulonglong2 t0 = b2v[0], t1 = b2v[1];
        o2a[0] = t0.x; o2a[1] = t0.y; o2a[2] = t1.x; o2a[3] = t1.y;
        o2b[0] = t0.x; o2b[1] = t0.y; o2b[2] = t1.x; o2b[3] = t1.y;
    }

    for (int hq = 0; hq < 4; hq++) {
        u64 aa[8], ab[8];
        {
            const ulonglong2* bq = reinterpret_cast<const ulonglong2*>(b1 + hq * 8);
            #pragma unroll
            for (int j = 0; j < 4; j++) {
                ulonglong2 t = bq[j];
                aa[2 * j] = t.x; aa[2 * j + 1] = t.y;
                ab[2 * j] = t.x; ab[2 * j + 1] = t.y;
            }
        }
        #pragma unroll
        for (int c = 0; c < 16; c++) {
            const ulonglong2* wv = reinterpret_cast<const ulonglong2*>(w1 + c * 32 + hq * 8);
            const u64 va = h2a[c], vb = h2b[c];
            #pragma unroll
            for (int j = 0; j < 4; j++) {
                ulonglong2 w = wv[j];
                aa[2 * j]     = fma2(va, w.x, aa[2 * j]);
                ab[2 * j]     = fma2(vb, w.x, ab[2 * j]);
                aa[2 * j + 1] = fma2(va, w.y, aa[2 * j + 1]);
                ab[2 * j + 1] = fma2(vb, w.y, ab[2 * j + 1]);
            }
        }
        #pragma unroll
        for (int h = 0; h < 8; h++) {
            float2 fa = up2(aa[h]), fb = up2(ab[h]);
            u64 ra = pk2(fmaxf(fa.x, 0.f), fmaxf(fa.y, 0.f));
            u64 rb = pk2(fmaxf(fb.x, 0.f), fmaxf(fb.y, 0.f));
            const ulonglong2* w2v = reinterpret_cast<const ulonglong2*>(w2 + (hq * 8 + h) * 4);
            ulonglong2 wa = w2v[0], wb = w2v[1];
            o2a[0] = fma2(ra, wa.x, o2a[0]); o2a[1] = fma2(ra, wa.y, o2a[1]);
            o2a[2] = fma2(ra, wb.x, o2a[2]); o2a[3] = fma2(ra, wb.y, o2a[3]);
            o2b[0] = fma2(rb, wa.x, o2b[0]); o2b[1] = fma2(rb, wa.y, o2b[1]);
            o2b[2] = fma2(rb, wb.x, o2b[2]); o2b[3] = fma2(rb, wb.y, o2b[3]);
        }
    }

    // residual update + clip, write the quad per channel as one 16B store
    const u64 P1 = 0x3DCCCCCD3DCCCCCDULL;   // (0.1f, 0.1f)
    #pragma unroll
    for (int cc = 0; cc < 4; cc++) {
        u64 na = fma2(o2a[cc], P1, h2a[2 * cc]);
        u64 nb = fma2(o2b[cc], P1, h2b[2 * cc]);
        float2 A = up2(na), B = up2(nb);
        float4 st;
        st.x = fminf(fmaxf(A.x, -1.f), 1.f);
        st.y = fminf(fmaxf(A.y, -1.f), 1.f);
        st.z = fminf(fmaxf(B.x, -1.f), 1.f);
        st.w = fminf(fmaxf(B.y, -1.f), 1.f);
        *reinterpret_cast<float4*>(nS + cc * S + cidx) = st;
    }
}

// SMEM layout (floats):
//  S0: 2*4*4096 = 32768   @ 0
//  S1: 2*4*512  = 4096    @ 32768
//  S2: 2*4*64   = 512     @ 36864
//  W1D (u64 dup): 3*16*32 = 1536 u64 @ 37376 (byte 149504, 16B aligned)
//  B1D: 96 u64 @ 40448 ; W2D: 384 u64 @ 40640 ; B2D: 12 u64 @ 41408
//  total 41432 floats = 165728 bytes
__global__ void __launch_bounds__(NT, 1) nca_kernel(
    const float* __restrict__ x,
    const float* __restrict__ w1g, const float* __restrict__ b1g,
    const float* __restrict__ w2g, const float* __restrict__ b2g,
    const float* __restrict__ clsw, const float* __restrict__ clsb,
    float* __restrict__ out)
{
    extern __shared__ float sm[];
    float* S0 = sm;
    float* S1 = sm + 32768;
    float* S2 = sm + 36864;
    u64* W1D = reinterpret_cast<u64*>(sm + 37376);
    u64* B1D = reinterpret_cast<u64*>(sm + 40448);
    u64* W2D = reinterpret_cast<u64*>(sm + 40640);
    u64* B2D = reinterpret_cast<u64*>(sm + 41408);

    const int tid = threadIdx.x;
    const int b = blockIdx.x;

    // load + duplicate-pack weights
    for (int i = tid; i < 1536; i += NT) { float w = w1g[i]; W1D[i] = pk2(w, w); }
    for (int i = tid; i < 96;   i += NT) { float w = b1g[i]; B1D[i] = pk2(w, w); }
    for (int i = tid; i < 384;  i += NT) { float w = w2g[i]; W2D[i] = pk2(w, w); }
    if (tid < 12) { float w = b2g[tid]; B2D[tid] = pk2(w, w); }

    // zero buf0 of all levels (buf1 is fully written by step 0)
    for (int i = tid; i < 16384; i += NT) S0[i] = 0.f;
    for (int i = tid; i < 2048;  i += NT) S1[i] = 0.f;
    for (int i = tid; i < 256;   i += NT) S2[i] = 0.f;
    __syncthreads();

    // input: thresholded pattern into channel 0, z = 8 slice of level 0, buf0
    {
        const float* xb = x + (size_t)b * 256;
        for (int i = tid; i < 256; i += NT) {
            S0[i * 16 + 8] = (xb[i] > 0.5f) ? 1.f : 0.f;
        }
    }
    __syncthreads();

    // 15 synchronous steps; quads: L0 1024, L1 128, L2 16 -> 1168 units
    for (int step = 0; step < 15; step++) {
        const int ob = step & 1;
        const int nb = ob ^ 1;
        const float* o0 = S0 + ob * 16384;  float* n0p = S0 + nb * 16384;
        const float* o1 = S1 + ob * 2048;   float* n1p = S1 + nb * 2048;
        const float* o2 = S2 + ob * 256;    float* n2p = S2 + nb * 256;

        for (int u = tid; u < 1168; u += NT) {
            if (u < 1024) {
                quad_cell(4, 0, 1, o0, nullptr, o1, n0p,
                          W1D, B1D, W2D, B2D, u);
            } else if (u < 1152) {
                quad_cell(3, 1, 1, o1, o0, o2, n1p,
                          W1D + 512, B1D + 32, W2D + 128, B2D + 4, u - 1024);
            } else {
                quad_cell(2, 1, 0, o2, o1, nullptr, n2p,
                          W1D + 1024, B1D + 64, W2D + 256, B2D + 8, u - 1152);
            }
        }
        __syncthreads();
    }

    // classification: feats = top level (buf1, after 15 steps), order (x,y,z,c)
    const float* top = S2 + 256;   // buf 1
    if (tid < 10) {
        float acc = clsb[tid];
        #pragma unroll 4
        for (int f = 0; f < 256; f++)
            acc += top[(f & 3) * 64 + (f >> 2)] * clsw[f * 10 + tid];
        out[(size_t)b * 10 + tid] = acc;
    }
}

extern "C" void kernel_launch(void* const* d_in, const int* in_sizes, int n_in,
                              void* d_out, int out_size) {
    const float* x   = (const float*)d_in[0];
    const float* w1  = (const float*)d_in[1];
    const float* b1  = (const float*)d_in[2];
    const float* w2  = (const float*)d_in[3];
    const float* b2  = (const float*)d_in[4];
    const float* cw  = (const float*)d_in[5];
    const float* cb  = (const float*)d_in[6];
    float* out = (float*)d_out;

    const int B = in_sizes[0] / 256;              // 2048
    const size_t smem = 41432 * sizeof(float);    // 165728 bytes

    cudaFuncSetAttribute(nca_kernel, cudaFuncAttributeMaxDynamicSharedMemorySize, (int)smem);
    nca_kernel<<<B, NT, smem>>>(x, w1, b1, w2, b2, cw, cb, out);
}